// round 4
// baseline (speedup 1.0000x reference)
#include <cuda_runtime.h>
#include <cuda_bf16.h>
#include <mma.h>
#include <math.h>

using namespace nvcuda;

// Problem dims
#define BATCH 16
#define SEQ   512
#define EMB   1024
#define FF    4096
#define HEADS 16
#define HDIM  64
#define ROWS  (BATCH*SEQ)        // 8192
#define BH    (BATCH*HEADS)      // 256

// ---------------- scratch (device globals; no allocation allowed) ----------------
__device__ float g_xln[ROWS*EMB];     // ln1 out / o-proj raw out (reused)
__device__ float g_q[ROWS*EMB];       // q / ln2 out (reused)
__device__ float g_k[ROWS*EMB];       // k / mlp raw out (reused)
__device__ float g_v[ROWS*EMB];
__device__ float g_attn[ROWS*EMB];
__device__ float g_x[ROWS*EMB];       // residual stream after attention
__device__ float g_h[ROWS*FF];        // mlp hidden
__device__ float g_scores[(size_t)BH*SEQ*SEQ]; // 256 MB

// ---------------- LayerNorm: 1 block per row, 256 threads, 1 float4/thread ----------------
__global__ void ln_kernel(const float* __restrict__ in, const float* __restrict__ gam,
                          const float* __restrict__ bet, float* __restrict__ out) {
    int row = blockIdx.x;
    int t = threadIdx.x;
    const float4* inr = reinterpret_cast<const float4*>(in + (size_t)row * EMB);
    float4 x = inr[t];
    float s  = x.x + x.y + x.z + x.w;
    float sq = x.x*x.x + x.y*x.y + x.z*x.z + x.w*x.w;
    // block reduce (256 thr = 8 warps)
    #pragma unroll
    for (int o = 16; o > 0; o >>= 1) {
        s  += __shfl_xor_sync(0xffffffffu, s,  o);
        sq += __shfl_xor_sync(0xffffffffu, sq, o);
    }
    __shared__ float sa[8], sb[8];
    int w = t >> 5, l = t & 31;
    if (l == 0) { sa[w] = s; sb[w] = sq; }
    __syncthreads();
    s = 0.f; sq = 0.f;
    #pragma unroll
    for (int i = 0; i < 8; i++) { s += sa[i]; sq += sb[i]; }
    float mean = s * (1.0f / EMB);
    float var  = sq * (1.0f / EMB) - mean * mean;
    float rstd = rsqrtf(var + 1e-5f);
    float4 g4 = reinterpret_cast<const float4*>(gam)[t];
    float4 b4 = reinterpret_cast<const float4*>(bet)[t];
    float4 o4;
    o4.x = (x.x - mean) * rstd * g4.x + b4.x;
    o4.y = (x.y - mean) * rstd * g4.y + b4.y;
    o4.z = (x.z - mean) * rstd * g4.z + b4.z;
    o4.w = (x.w - mean) * rstd * g4.w + b4.w;
    reinterpret_cast<float4*>(out + (size_t)row * EMB)[t] = o4;
}

// ---------------- TF32 wmma GEMM: C[M,N] = A[M,K] * B[K,N]  (all row-major) ----------------
// block tile 128x128, BK=16, 8 warps (2x4), warp tile 64x32 = 4x2 frags of 16x16x8.
__global__ void gemm_tf32_kernel(const float* __restrict__ A, const float* __restrict__ B,
                                 float* __restrict__ C, int M, int N, int K) {
    __shared__ float As[128][20];   // pad to 20 (mult of 4)
    __shared__ float Bs[16][132];   // pad to 132 (mult of 4)
    int m0 = blockIdx.y * 128;
    int n0 = blockIdx.x * 128;
    int tid  = threadIdx.x;
    int warp = tid >> 5;
    int wm = warp >> 2;       // 0..1
    int wn = warp & 3;        // 0..3

    wmma::fragment<wmma::accumulator, 16, 16, 8, float> acc[4][2];
    #pragma unroll
    for (int i = 0; i < 4; i++)
        #pragma unroll
        for (int j = 0; j < 2; j++)
            wmma::fill_fragment(acc[i][j], 0.0f);

    int rowA = tid >> 2;              // 0..63
    int colA = (tid & 3) << 2;        // 0,4,8,12
    int rowB = tid >> 5;              // 0..7
    int colB = (tid & 31) << 2;       // 0..124

    for (int k0 = 0; k0 < K; k0 += 16) {
        *reinterpret_cast<float4*>(&As[rowA][colA]) =
            *reinterpret_cast<const float4*>(&A[(size_t)(m0 + rowA) * K + k0 + colA]);
        *reinterpret_cast<float4*>(&As[rowA + 64][colA]) =
            *reinterpret_cast<const float4*>(&A[(size_t)(m0 + rowA + 64) * K + k0 + colA]);
        *reinterpret_cast<float4*>(&Bs[rowB][colB]) =
            *reinterpret_cast<const float4*>(&B[(size_t)(k0 + rowB) * N + n0 + colB]);
        *reinterpret_cast<float4*>(&Bs[rowB + 8][colB]) =
            *reinterpret_cast<const float4*>(&B[(size_t)(k0 + rowB + 8) * N + n0 + colB]);
        __syncthreads();

        #pragma unroll
        for (int k8 = 0; k8 < 2; k8++) {
            wmma::fragment<wmma::matrix_a, 16, 16, 8, wmma::precision::tf32, wmma::row_major> af[4];
            wmma::fragment<wmma::matrix_b, 16, 16, 8, wmma::precision::tf32, wmma::row_major> bf[2];
            #pragma unroll
            for (int i = 0; i < 4; i++) {
                wmma::load_matrix_sync(af[i], &As[wm * 64 + i * 16][k8 * 8], 20);
                #pragma unroll
                for (int e = 0; e < af[i].num_elements; e++)
                    af[i].x[e] = wmma::__float_to_tf32(af[i].x[e]);
            }
            #pragma unroll
            for (int j = 0; j < 2; j++) {
                wmma::load_matrix_sync(bf[j], &Bs[k8 * 8][wn * 32 + j * 16], 132);
                #pragma unroll
                for (int e = 0; e < bf[j].num_elements; e++)
                    bf[j].x[e] = wmma::__float_to_tf32(bf[j].x[e]);
            }
            #pragma unroll
            for (int i = 0; i < 4; i++)
                #pragma unroll
                for (int j = 0; j < 2; j++)
                    wmma::mma_sync(acc[i][j], af[i], bf[j], acc[i][j]);
        }
        __syncthreads();
    }

    #pragma unroll
    for (int i = 0; i < 4; i++)
        #pragma unroll
        for (int j = 0; j < 2; j++)
            wmma::store_matrix_sync(&C[(size_t)(m0 + wm * 64 + i * 16) * N + n0 + wn * 32 + j * 16],
                                    acc[i][j], N, wmma::mem_row_major);
}

// ---------------- elementwise epilogues ----------------
// out = c + bias[col] (+ res).  All sizes multiple of (256*4) elements.
__global__ void bias_res_kernel(const float* __restrict__ c, const float* __restrict__ bias,
                                const float* __restrict__ res, float* __restrict__ out,
                                int ncols4) {
    size_t i4 = (size_t)blockIdx.x * blockDim.x + threadIdx.x;
    float4 v = reinterpret_cast<const float4*>(c)[i4];
    float4 b = reinterpret_cast<const float4*>(bias)[i4 % ncols4];
    v.x += b.x; v.y += b.y; v.z += b.z; v.w += b.w;
    if (res) {
        float4 r = reinterpret_cast<const float4*>(res)[i4];
        v.x += r.x; v.y += r.y; v.z += r.z; v.w += r.w;
    }
    reinterpret_cast<float4*>(out)[i4] = v;
}

__global__ void bias_gelu_kernel(float* __restrict__ c, const float* __restrict__ bias,
                                 int ncols4) {
    size_t i4 = (size_t)blockIdx.x * blockDim.x + threadIdx.x;
    float4 v = reinterpret_cast<float4*>(c)[i4];
    float4 b = reinterpret_cast<const float4*>(bias)[i4 % ncols4];
    const float is2 = 0.70710678118654752f;
    float y;
    y = v.x + b.x; v.x = 0.5f * y * (1.0f + erff(y * is2));
    y = v.y + b.y; v.y = 0.5f * y * (1.0f + erff(y * is2));
    y = v.z + b.z; v.z = 0.5f * y * (1.0f + erff(y * is2));
    y = v.w + b.w; v.w = 0.5f * y * (1.0f + erff(y * is2));
    reinterpret_cast<float4*>(c)[i4] = v;
}

// ---------------- attention: scores = Q K^T * scale ----------------
// grid (ktile=8, qtile=8, bh=256), 256 threads as 16x16, 4x4 per-thread micro tile.
__global__ void scores_kernel(const float* __restrict__ q, const float* __restrict__ k,
                              float* __restrict__ scores) {
    int bh = blockIdx.z;
    int b = bh >> 4, h = bh & 15;
    int q0 = blockIdx.y * 64, k0 = blockIdx.x * 64;
    __shared__ float Qs[64][65], Ks[64][65];
    int tid = threadIdx.x;
    int r = tid >> 2;
    int c4 = tid & 3;
    {
        const float* qb = q + ((size_t)(b * SEQ + q0 + r) * HEADS + h) * HDIM;
        const float* kb = k + ((size_t)(b * SEQ + k0 + r) * HEADS + h) * HDIM;
        #pragma unroll
        for (int i = 0; i < 4; i++) {
            int c = (c4 + i * 4) * 4;
            float4 a = *reinterpret_cast<const float4*>(&qb[c]);
            Qs[r][c] = a.x; Qs[r][c+1] = a.y; Qs[r][c+2] = a.z; Qs[r][c+3] = a.w;
            float4 bb = *reinterpret_cast<const float4*>(&kb[c]);
            Ks[r][c] = bb.x; Ks[r][c+1] = bb.y; Ks[r][c+2] = bb.z; Ks[r][c+3] = bb.w;
        }
    }
    __syncthreads();
    int ty = tid >> 4, tx = tid & 15;
    float acc[4][4] = {};
    #pragma unroll 8
    for (int kk = 0; kk < 64; kk++) {
        float a[4], bb[4];
        #pragma unroll
        for (int i = 0; i < 4; i++) a[i]  = Qs[ty * 4 + i][kk];
        #pragma unroll
        for (int j = 0; j < 4; j++) bb[j] = Ks[tx * 4 + j][kk];
        #pragma unroll
        for (int i = 0; i < 4; i++)
            #pragma unroll
            for (int j = 0; j < 4; j++)
                acc[i][j] += a[i] * bb[j];
    }
    const float scale = 0.125f; // 1/sqrt(64)
    #pragma unroll
    for (int i = 0; i < 4; i++) {
        size_t rowoff = ((size_t)bh * SEQ + q0 + ty * 4 + i) * SEQ + k0 + tx * 4;
        float4 o;
        o.x = acc[i][0] * scale; o.y = acc[i][1] * scale;
        o.z = acc[i][2] * scale; o.w = acc[i][3] * scale;
        *reinterpret_cast<float4*>(&scores[rowoff]) = o;
    }
}

// ---------------- softmax over rows of 512 (1 block per row, 128 threads) ----------------
__global__ void softmax_kernel(float* __restrict__ s) {
    size_t row = blockIdx.x;
    float* p = s + row * SEQ;
    int t = threadIdx.x;
    float4 x = reinterpret_cast<float4*>(p)[t];
    float m = fmaxf(fmaxf(x.x, x.y), fmaxf(x.z, x.w));
    #pragma unroll
    for (int o = 16; o > 0; o >>= 1) m = fmaxf(m, __shfl_xor_sync(0xffffffffu, m, o));
    __shared__ float sm[4], ss[4];
    int w = t >> 5, l = t & 31;
    if (l == 0) sm[w] = m;
    __syncthreads();
    m = fmaxf(fmaxf(sm[0], sm[1]), fmaxf(sm[2], sm[3]));
    x.x = __expf(x.x - m); x.y = __expf(x.y - m);
    x.z = __expf(x.z - m); x.w = __expf(x.w - m);
    float sum = x.x + x.y + x.z + x.w;
    #pragma unroll
    for (int o = 16; o > 0; o >>= 1) sum += __shfl_xor_sync(0xffffffffu, sum, o);
    if (l == 0) ss[w] = sum;
    __syncthreads();
    sum = ss[0] + ss[1] + ss[2] + ss[3];
    float inv = 1.0f / sum;
    x.x *= inv; x.y *= inv; x.z *= inv; x.w *= inv;
    reinterpret_cast<float4*>(p)[t] = x;
}

// ---------------- attention: out = P V  (per head, 64 q-rows per block) ----------------
// grid (qtile=8, bh=256), 256 threads as 16x16, K loop 512 in chunks of 64.
__global__ void av_kernel(const float* __restrict__ scores, const float* __restrict__ v,
                          float* __restrict__ out) {
    int bh = blockIdx.y;
    int b = bh >> 4, h = bh & 15;
    int q0 = blockIdx.x * 64;
    __shared__ float Ps[64][65], Vs[64][65];
    int tid = threadIdx.x;
    int r = tid >> 2;
    int c4 = tid & 3;
    int ty = tid >> 4, tx = tid & 15;
    float acc[4][4] = {};
    for (int kc = 0; kc < SEQ; kc += 64) {
        const float* pb = scores + ((size_t)bh * SEQ + q0 + r) * SEQ + kc;
        const float* vb = v + ((size_t)(b * SEQ + kc + r) * HEADS + h) * HDIM;
        #pragma unroll
        for (int i = 0; i < 4; i++) {
            int c = (c4 + i * 4) * 4;
            float4 a = *reinterpret_cast<const float4*>(&pb[c]);
            Ps[r][c] = a.x; Ps[r][c+1] = a.y; Ps[r][c+2] = a.z; Ps[r][c+3] = a.w;
            float4 bb = *reinterpret_cast<const float4*>(&vb[c]);
            Vs[r][c] = bb.x; Vs[r][c+1] = bb.y; Vs[r][c+2] = bb.z; Vs[r][c+3] = bb.w;
        }
        __syncthreads();
        #pragma unroll 8
        for (int kk = 0; kk < 64; kk++) {
            float a[4], bb[4];
            #pragma unroll
            for (int i = 0; i < 4; i++) a[i]  = Ps[ty * 4 + i][kk];
            #pragma unroll
            for (int j = 0; j < 4; j++) bb[j] = Vs[kk][tx * 4 + j];
            #pragma unroll
            for (int i = 0; i < 4; i++)
                #pragma unroll
                for (int j = 0; j < 4; j++)
                    acc[i][j] += a[i] * bb[j];
        }
        __syncthreads();
    }
    #pragma unroll
    for (int i = 0; i < 4; i++) {
        size_t off = ((size_t)(b * SEQ + q0 + ty * 4 + i) * HEADS + h) * HDIM + tx * 4;
        float4 o;
        o.x = acc[i][0]; o.y = acc[i][1]; o.z = acc[i][2]; o.w = acc[i][3];
        *reinterpret_cast<float4*>(&out[off]) = o;
    }
}

// ---------------- driver ----------------
extern "C" void kernel_launch(void* const* d_in, const int* in_sizes, int n_in,
                              void* d_out, int out_size) {
    const float* input = (const float*)d_in[0];
    const float* ln1_g = (const float*)d_in[1];
    const float* ln1_b = (const float*)d_in[2];
    const float* wq    = (const float*)d_in[3];
    const float* bq    = (const float*)d_in[4];
    const float* wk    = (const float*)d_in[5];
    const float* bk    = (const float*)d_in[6];
    const float* wv    = (const float*)d_in[7];
    const float* bv    = (const float*)d_in[8];
    const float* wo    = (const float*)d_in[9];
    const float* bo    = (const float*)d_in[10];
    const float* ln2_g = (const float*)d_in[11];
    const float* ln2_b = (const float*)d_in[12];
    const float* w1    = (const float*)d_in[13];
    const float* b1    = (const float*)d_in[14];
    const float* w2    = (const float*)d_in[15];
    const float* b2    = (const float*)d_in[16];
    float* out = (float*)d_out;

    float *xln, *q, *k, *v, *attn, *x, *h, *scores;
    cudaGetSymbolAddress((void**)&xln,    g_xln);
    cudaGetSymbolAddress((void**)&q,      g_q);
    cudaGetSymbolAddress((void**)&k,      g_k);
    cudaGetSymbolAddress((void**)&v,      g_v);
    cudaGetSymbolAddress((void**)&attn,   g_attn);
    cudaGetSymbolAddress((void**)&x,      g_x);
    cudaGetSymbolAddress((void**)&h,      g_h);
    cudaGetSymbolAddress((void**)&scores, g_scores);

    const int E4 = EMB / 4;   // 256
    const int F4 = FF / 4;    // 1024
    const int nE4blk = ROWS * E4 / 256;   // elementwise blocks for [ROWS,EMB]
    const int nF4blk = ROWS * F4 / 256;   // for [ROWS,FF]

    dim3 gemmE(EMB / 128, ROWS / 128);    // (8, 64)
    dim3 gemmF(FF / 128, ROWS / 128);     // (32, 64)

    // 1) LN1
    ln_kernel<<<ROWS, 256>>>(input, ln1_g, ln1_b, xln);
    // 2) QKV projections (tf32), then bias
    gemm_tf32_kernel<<<gemmE, 256>>>(xln, wq, q, ROWS, EMB, EMB);
    gemm_tf32_kernel<<<gemmE, 256>>>(xln, wk, k, ROWS, EMB, EMB);
    gemm_tf32_kernel<<<gemmE, 256>>>(xln, wv, v, ROWS, EMB, EMB);
    bias_res_kernel<<<nE4blk, 256>>>(q, bq, nullptr, q, E4);
    bias_res_kernel<<<nE4blk, 256>>>(k, bk, nullptr, k, E4);
    bias_res_kernel<<<nE4blk, 256>>>(v, bv, nullptr, v, E4);
    // 3) attention
    scores_kernel<<<dim3(8, 8, BH), 256>>>(q, k, scores);
    softmax_kernel<<<BH * SEQ, 128>>>(scores);
    av_kernel<<<dim3(8, BH), 256>>>(scores, v, attn);
    // 4) output projection + residual  (xln buffer reused as raw GEMM out)
    gemm_tf32_kernel<<<gemmE, 256>>>(attn, wo, xln, ROWS, EMB, EMB);
    bias_res_kernel<<<nE4blk, 256>>>(xln, bo, input, x, E4);
    // 5) LN2 (into q buffer, reused)
    ln_kernel<<<ROWS, 256>>>(x, ln2_g, ln2_b, q);
    // 6) MLP up + GELU
    gemm_tf32_kernel<<<gemmF, 256>>>(q, w1, h, ROWS, FF, EMB);
    bias_gelu_kernel<<<nF4blk, 256>>>(h, b1, F4);
    // 7) MLP down + bias + residual -> out   (k buffer reused as raw GEMM out)
    gemm_tf32_kernel<<<gemmE, 256>>>(h, w2, k, ROWS, EMB, FF);
    bias_res_kernel<<<nE4blk, 256>>>(k, b2, x, out, E4);
}

// round 7
// speedup vs baseline: 1.1972x; 1.1972x over previous
#include <cuda_runtime.h>
#include <cuda_bf16.h>
#include <mma.h>
#include <math.h>
#include <cstdint>

using namespace nvcuda;

// Problem dims
#define BATCH 16
#define SEQ   512
#define EMB   1024
#define FF    4096
#define HEADS 16
#define HDIM  64
#define ROWS  (BATCH*SEQ)        // 8192
#define BH    (BATCH*HEADS)      // 256

// ---------------- scratch (device globals; no allocation allowed) ----------------
__device__ float g_xln[ROWS*EMB];
__device__ float g_q[ROWS*EMB];
__device__ float g_k[ROWS*EMB];
__device__ float g_v[ROWS*EMB];
__device__ float g_attn[ROWS*EMB];
__device__ float g_x[ROWS*EMB];
__device__ float g_h[ROWS*FF];
__device__ float g_scores[(size_t)BH*SEQ*SEQ];

// ---------------- cp.async helpers ----------------
__device__ __forceinline__ void cp_async16(void* smem_dst, const void* gsrc) {
    unsigned s = (unsigned)__cvta_generic_to_shared(smem_dst);
    asm volatile("cp.async.cg.shared.global [%0], [%1], 16;\n" :: "r"(s), "l"(gsrc));
}
__device__ __forceinline__ void cp_commit() {
    asm volatile("cp.async.commit_group;\n");
}

__device__ __forceinline__ float gelu_exact(float y) {
    return 0.5f * y * (1.0f + erff(y * 0.70710678118654752f));
}

// ---------------- LayerNorm: 1 block per row, 256 threads ----------------
__global__ void ln_kernel(const float* __restrict__ in, const float* __restrict__ gam,
                          const float* __restrict__ bet, float* __restrict__ out) {
    int row = blockIdx.x;
    int t = threadIdx.x;
    const float4* inr = reinterpret_cast<const float4*>(in + (size_t)row * EMB);
    float4 x = inr[t];
    float s  = x.x + x.y + x.z + x.w;
    float sq = x.x*x.x + x.y*x.y + x.z*x.z + x.w*x.w;
    #pragma unroll
    for (int o = 16; o > 0; o >>= 1) {
        s  += __shfl_xor_sync(0xffffffffu, s,  o);
        sq += __shfl_xor_sync(0xffffffffu, sq, o);
    }
    __shared__ float sa[8], sb[8];
    int w = t >> 5, l = t & 31;
    if (l == 0) { sa[w] = s; sb[w] = sq; }
    __syncthreads();
    s = 0.f; sq = 0.f;
    #pragma unroll
    for (int i = 0; i < 8; i++) { s += sa[i]; sq += sb[i]; }
    float mean = s * (1.0f / EMB);
    float var  = sq * (1.0f / EMB) - mean * mean;
    float rstd = rsqrtf(var + 1e-5f);
    float4 g4 = reinterpret_cast<const float4*>(gam)[t];
    float4 b4 = reinterpret_cast<const float4*>(bet)[t];
    float4 o4;
    o4.x = (x.x - mean) * rstd * g4.x + b4.x;
    o4.y = (x.y - mean) * rstd * g4.y + b4.y;
    o4.z = (x.z - mean) * rstd * g4.z + b4.z;
    o4.w = (x.w - mean) * rstd * g4.w + b4.w;
    reinterpret_cast<float4*>(out + (size_t)row * EMB)[t] = o4;
}

// ---------------- TF32 GEMM, double-buffered cp.async, fused epilogue ----------------
// C[M,N] = A[M,K] * B[K,N] (row-major). Block tile 128x128, BK=32, 8 warps (2x4),
// warp tile 64x32 = 4x2 frags m16n16k8. EPI: 0 = +bias, 1 = +bias,GELU, 2 = +bias,+res.
#define ALD 36
#define BLD 132
#define GEMM_SMEM ((2*128*ALD + 2*32*BLD) * 4)   // 70656 bytes

template<int EPI>
__global__ __launch_bounds__(256, 2)
void gemm_dbuf(const float* __restrict__ A, const float* __restrict__ B,
               const float* __restrict__ bias, const float* __restrict__ res,
               float* __restrict__ C, int M, int N, int K) {
    extern __shared__ float smbuf[];
    float* As[2] = { smbuf, smbuf + 128*ALD };
    float* Bs[2] = { smbuf + 2*128*ALD, smbuf + 2*128*ALD + 32*BLD };
    float* Cs = smbuf;   // epilogue alias: [128][BLD]

    const int m0 = blockIdx.y * 128;
    const int n0 = blockIdx.x * 128;
    const int tid = threadIdx.x;
    const int warp = tid >> 5;
    const int wm = warp >> 2;      // 0..1
    const int wn = warp & 3;       // 0..3

    wmma::fragment<wmma::accumulator, 16, 16, 8, float> acc[4][2];
    #pragma unroll
    for (int i = 0; i < 4; i++)
        #pragma unroll
        for (int j = 0; j < 2; j++)
            wmma::fill_fragment(acc[i][j], 0.0f);

    auto load_stage = [&](int st, int k0) {
        #pragma unroll
        for (int p = 0; p < 4; p++) {              // A: 128 x 8 float4
            int idx = tid + p * 256;
            int r = idx >> 3, c = (idx & 7) << 2;
            cp_async16(As[st] + r * ALD + c, A + (size_t)(m0 + r) * K + k0 + c);
        }
        #pragma unroll
        for (int p = 0; p < 4; p++) {              // B: 32 x 32 float4
            int idx = tid + p * 256;
            int r = idx >> 5, c = (idx & 31) << 2;
            cp_async16(Bs[st] + r * BLD + c, B + (size_t)(k0 + r) * N + n0 + c);
        }
        cp_commit();
    };

    const int NT = K >> 5;
    load_stage(0, 0);

    for (int kt = 0; kt < NT; kt++) {
        if (kt + 1 < NT) {
            load_stage((kt + 1) & 1, (kt + 1) << 5);
            asm volatile("cp.async.wait_group 1;\n");
        } else {
            asm volatile("cp.async.wait_group 0;\n");
        }
        __syncthreads();
        const float* as = As[kt & 1];
        const float* bs = Bs[kt & 1];
        #pragma unroll
        for (int k8 = 0; k8 < 4; k8++) {
            wmma::fragment<wmma::matrix_a, 16, 16, 8, wmma::precision::tf32, wmma::row_major> af[4];
            wmma::fragment<wmma::matrix_b, 16, 16, 8, wmma::precision::tf32, wmma::row_major> bf[2];
            #pragma unroll
            for (int i = 0; i < 4; i++) {
                wmma::load_matrix_sync(af[i], as + (wm * 64 + i * 16) * ALD + k8 * 8, ALD);
                #pragma unroll
                for (int e = 0; e < af[i].num_elements; e++)
                    af[i].x[e] = wmma::__float_to_tf32(af[i].x[e]);
            }
            #pragma unroll
            for (int j = 0; j < 2; j++) {
                wmma::load_matrix_sync(bf[j], bs + (k8 * 8) * BLD + wn * 32 + j * 16, BLD);
                #pragma unroll
                for (int e = 0; e < bf[j].num_elements; e++)
                    bf[j].x[e] = wmma::__float_to_tf32(bf[j].x[e]);
            }
            #pragma unroll
            for (int i = 0; i < 4; i++)
                #pragma unroll
                for (int j = 0; j < 2; j++)
                    wmma::mma_sync(acc[i][j], af[i], bf[j], acc[i][j]);
        }
        __syncthreads();
    }

    // epilogue: acc -> smem -> (bias / gelu / res) -> global
    #pragma unroll
    for (int i = 0; i < 4; i++)
        #pragma unroll
        for (int j = 0; j < 2; j++)
            wmma::store_matrix_sync(Cs + (wm * 64 + i * 16) * BLD + wn * 32 + j * 16,
                                    acc[i][j], BLD, wmma::mem_row_major);
    __syncthreads();

    #pragma unroll
    for (int p = 0; p < 16; p++) {
        int idx = tid + p * 256;              // 128 rows x 32 float4
        int r = idx >> 5, c = (idx & 31) << 2;
        float4 v = *reinterpret_cast<const float4*>(Cs + r * BLD + c);
        float4 b = *reinterpret_cast<const float4*>(bias + n0 + c);
        v.x += b.x; v.y += b.y; v.z += b.z; v.w += b.w;
        if (EPI == 1) {
            v.x = gelu_exact(v.x); v.y = gelu_exact(v.y);
            v.z = gelu_exact(v.z); v.w = gelu_exact(v.w);
        }
        if (EPI == 2) {
            float4 rr = *reinterpret_cast<const float4*>(res + (size_t)(m0 + r) * N + n0 + c);
            v.x += rr.x; v.y += rr.y; v.z += rr.z; v.w += rr.w;
        }
        *reinterpret_cast<float4*>(C + (size_t)(m0 + r) * N + n0 + c) = v;
    }
}

// ---------------- attention scores = (Q K^T) * 1/8, TF32 wmma ----------------
// grid (ktile=4, qtile=4, bh=256), 256 thr, tile 128x128, K=64 resident in smem.
#define QLD 68
#define SCORES_SMEM (2*128*QLD*4)   // 69632

__global__ __launch_bounds__(256, 2)
void scores_wmma(const float* __restrict__ q, const float* __restrict__ k,
                 float* __restrict__ s) {
    extern __shared__ float smbuf[];
    float* Qs = smbuf;            // [128][QLD]
    float* Ks = smbuf + 128*QLD;  // [128][QLD]
    int bh = blockIdx.z;
    int b = bh >> 4, h = bh & 15;
    int q0 = blockIdx.y * 128, k0 = blockIdx.x * 128;
    int tid = threadIdx.x;
    const float* qbase = q + (size_t)(b * SEQ + q0) * EMB + h * HDIM;
    const float* kbase = k + (size_t)(b * SEQ + k0) * EMB + h * HDIM;
    #pragma unroll
    for (int p = 0; p < 8; p++) {
        int idx = tid + p * 256;               // 128 rows x 16 float4
        int r = idx >> 4, c = (idx & 15) << 2;
        *reinterpret_cast<float4*>(Qs + r * QLD + c) =
            *reinterpret_cast<const float4*>(qbase + (size_t)r * EMB + c);
        *reinterpret_cast<float4*>(Ks + r * QLD + c) =
            *reinterpret_cast<const float4*>(kbase + (size_t)r * EMB + c);
    }
    __syncthreads();

    int warp = tid >> 5, wm = warp >> 2, wn = warp & 3;
    wmma::fragment<wmma::accumulator, 16, 16, 8, float> acc[4][2];
    #pragma unroll
    for (int i = 0; i < 4; i++)
        #pragma unroll
        for (int j = 0; j < 2; j++)
            wmma::fill_fragment(acc[i][j], 0.0f);

    #pragma unroll
    for (int k8 = 0; k8 < 8; k8++) {
        wmma::fragment<wmma::matrix_a, 16, 16, 8, wmma::precision::tf32, wmma::row_major> af[4];
        wmma::fragment<wmma::matrix_b, 16, 16, 8, wmma::precision::tf32, wmma::col_major> bf[2];
        #pragma unroll
        for (int i = 0; i < 4; i++) {
            wmma::load_matrix_sync(af[i], Qs + (wm * 64 + i * 16) * QLD + k8 * 8, QLD);
            #pragma unroll
            for (int e = 0; e < af[i].num_elements; e++)
                af[i].x[e] = wmma::__float_to_tf32(af[i].x[e]);
        }
        #pragma unroll
        for (int j = 0; j < 2; j++) {
            // B = K^T: element (kk, n) lives at Ks[n][kk] -> col_major, ld QLD
            wmma::load_matrix_sync(bf[j], Ks + (wn * 32 + j * 16) * QLD + k8 * 8, QLD);
            #pragma unroll
            for (int e = 0; e < bf[j].num_elements; e++)
                bf[j].x[e] = wmma::__float_to_tf32(bf[j].x[e]);
        }
        #pragma unroll
        for (int i = 0; i < 4; i++)
            #pragma unroll
            for (int j = 0; j < 2; j++)
                wmma::mma_sync(acc[i][j], af[i], bf[j], acc[i][j]);
    }

    #pragma unroll
    for (int i = 0; i < 4; i++)
        #pragma unroll
        for (int j = 0; j < 2; j++) {
            #pragma unroll
            for (int e = 0; e < acc[i][j].num_elements; e++)
                acc[i][j].x[e] *= 0.125f;
            wmma::store_matrix_sync(
                s + ((size_t)bh * SEQ + q0 + wm * 64 + i * 16) * SEQ + k0 + wn * 32 + j * 16,
                acc[i][j], SEQ, wmma::mem_row_major);
        }
}

// ---------------- softmax over rows of 512 ----------------
__global__ void softmax_kernel(float* __restrict__ s) {
    size_t row = blockIdx.x;
    float* p = s + row * SEQ;
    int t = threadIdx.x;
    float4 x = reinterpret_cast<float4*>(p)[t];
    float m = fmaxf(fmaxf(x.x, x.y), fmaxf(x.z, x.w));
    #pragma unroll
    for (int o = 16; o > 0; o >>= 1) m = fmaxf(m, __shfl_xor_sync(0xffffffffu, m, o));
    __shared__ float sm[4], ss[4];
    int w = t >> 5, l = t & 31;
    if (l == 0) sm[w] = m;
    __syncthreads();
    m = fmaxf(fmaxf(sm[0], sm[1]), fmaxf(sm[2], sm[3]));
    x.x = __expf(x.x - m); x.y = __expf(x.y - m);
    x.z = __expf(x.z - m); x.w = __expf(x.w - m);
    float sum = x.x + x.y + x.z + x.w;
    #pragma unroll
    for (int o = 16; o > 0; o >>= 1) sum += __shfl_xor_sync(0xffffffffu, sum, o);
    if (l == 0) ss[w] = sum;
    __syncthreads();
    sum = ss[0] + ss[1] + ss[2] + ss[3];
    float inv = 1.0f / sum;
    x.x *= inv; x.y *= inv; x.z *= inv; x.w *= inv;
    reinterpret_cast<float4*>(p)[t] = x;
}

// ---------------- AV: out = P V, TF32 wmma ----------------
// grid (qtile=4, bh=256), 256 thr. Tile 128 q-rows x 64 d-cols, K chunks of 64.
// 8 warps as 4x2: warp tile 32x32 = 2x2 frags.
#define AV_SMEM ((128*QLD + 64*QLD) * 4)   // 52224

__global__ __launch_bounds__(256, 2)
void av_wmma(const float* __restrict__ s, const float* __restrict__ v,
             float* __restrict__ o) {
    extern __shared__ float smbuf[];
    float* Ps = smbuf;            // [128][QLD]
    float* Vs = smbuf + 128*QLD;  // [64][QLD]
    int bh = blockIdx.y;
    int b = bh >> 4, h = bh & 15;
    int q0 = blockIdx.x * 128;
    int tid = threadIdx.x;
    int warp = tid >> 5, wm = warp >> 1, wn = warp & 1;

    wmma::fragment<wmma::accumulator, 16, 16, 8, float> acc[2][2];
    #pragma unroll
    for (int i = 0; i < 2; i++)
        #pragma unroll
        for (int j = 0; j < 2; j++)
            wmma::fill_fragment(acc[i][j], 0.0f);

    for (int kc = 0; kc < SEQ; kc += 64) {
        #pragma unroll
        for (int p = 0; p < 8; p++) {              // P: 128 x 16 float4
            int idx = tid + p * 256;
            int r = idx >> 4, c = (idx & 15) << 2;
            *reinterpret_cast<float4*>(Ps + r * QLD + c) =
                *reinterpret_cast<const float4*>(s + ((size_t)bh * SEQ + q0 + r) * SEQ + kc + c);
        }
        #pragma unroll
        for (int p = 0; p < 4; p++) {              // V: 64 x 16 float4
            int idx = tid + p * 256;
            int r = idx >> 4, c = (idx & 15) << 2;
            *reinterpret_cast<float4*>(Vs + r * QLD + c) =
                *reinterpret_cast<const float4*>(v + (size_t)(b * SEQ + kc + r) * EMB + h * HDIM + c);
        }
        __syncthreads();
        #pragma unroll
        for (int k8 = 0; k8 < 8; k8++) {
            wmma::fragment<wmma::matrix_a, 16, 16, 8, wmma::precision::tf32, wmma::row_major> af[2];
            wmma::fragment<wmma::matrix_b, 16, 16, 8, wmma::precision::tf32, wmma::row_major> bf[2];
            #pragma unroll
            for (int i = 0; i < 2; i++) {
                wmma::load_matrix_sync(af[i], Ps + (wm * 32 + i * 16) * QLD + k8 * 8, QLD);
                #pragma unroll
                for (int e = 0; e < af[i].num_elements; e++)
                    af[i].x[e] = wmma::__float_to_tf32(af[i].x[e]);
            }
            #pragma unroll
            for (int j = 0; j < 2; j++) {
                wmma::load_matrix_sync(bf[j], Vs + (k8 * 8) * QLD + wn * 32 + j * 16, QLD);
                #pragma unroll
                for (int e = 0; e < bf[j].num_elements; e++)
                    bf[j].x[e] = wmma::__float_to_tf32(bf[j].x[e]);
            }
            #pragma unroll
            for (int i = 0; i < 2; i++)
                #pragma unroll
                for (int j = 0; j < 2; j++)
                    wmma::mma_sync(acc[i][j], af[i], bf[j], acc[i][j]);
        }
        __syncthreads();
    }

    #pragma unroll
    for (int i = 0; i < 2; i++)
        #pragma unroll
        for (int j = 0; j < 2; j++)
            wmma::store_matrix_sync(
                o + (size_t)(b * SEQ + q0 + wm * 32 + i * 16) * EMB + h * HDIM + wn * 32 + j * 16,
                acc[i][j], EMB, wmma::mem_row_major);
}

// ---------------- driver ----------------
extern "C" void kernel_launch(void* const* d_in, const int* in_sizes, int n_in,
                              void* d_out, int out_size) {
    const float* input = (const float*)d_in[0];
    const float* ln1_g = (const float*)d_in[1];
    const float* ln1_b = (const float*)d_in[2];
    const float* wq    = (const float*)d_in[3];
    const float* bq    = (const float*)d_in[4];
    const float* wk    = (const float*)d_in[5];
    const float* bk    = (const float*)d_in[6];
    const float* wv    = (const float*)d_in[7];
    const float* bv    = (const float*)d_in[8];
    const float* wo    = (const float*)d_in[9];
    const float* bo    = (const float*)d_in[10];
    const float* ln2_g = (const float*)d_in[11];
    const float* ln2_b = (const float*)d_in[12];
    const float* w1    = (const float*)d_in[13];
    const float* b1    = (const float*)d_in[14];
    const float* w2    = (const float*)d_in[15];
    const float* b2    = (const float*)d_in[16];
    float* out = (float*)d_out;

    float *xln, *q, *k, *v, *attn, *x, *h, *scores;
    cudaGetSymbolAddress((void**)&xln,    g_xln);
    cudaGetSymbolAddress((void**)&q,      g_q);
    cudaGetSymbolAddress((void**)&k,      g_k);
    cudaGetSymbolAddress((void**)&v,      g_v);
    cudaGetSymbolAddress((void**)&attn,   g_attn);
    cudaGetSymbolAddress((void**)&x,      g_x);
    cudaGetSymbolAddress((void**)&h,      g_h);
    cudaGetSymbolAddress((void**)&scores, g_scores);

    cudaFuncSetAttribute(gemm_dbuf<0>, cudaFuncAttributeMaxDynamicSharedMemorySize, GEMM_SMEM);
    cudaFuncSetAttribute(gemm_dbuf<1>, cudaFuncAttributeMaxDynamicSharedMemorySize, GEMM_SMEM);
    cudaFuncSetAttribute(gemm_dbuf<2>, cudaFuncAttributeMaxDynamicSharedMemorySize, GEMM_SMEM);
    cudaFuncSetAttribute(scores_wmma,  cudaFuncAttributeMaxDynamicSharedMemorySize, SCORES_SMEM);
    cudaFuncSetAttribute(av_wmma,      cudaFuncAttributeMaxDynamicSharedMemorySize, AV_SMEM);

    dim3 gemmE(EMB / 128, ROWS / 128);    // (8, 64)
    dim3 gemmF(FF / 128, ROWS / 128);     // (32, 64)

    // 1) LN1
    ln_kernel<<<ROWS, 256>>>(input, ln1_g, ln1_b, xln);
    // 2) QKV projections with fused bias
    gemm_dbuf<0><<<gemmE, 256, GEMM_SMEM>>>(xln, wq, bq, nullptr, q, ROWS, EMB, EMB);
    gemm_dbuf<0><<<gemmE, 256, GEMM_SMEM>>>(xln, wk, bk, nullptr, k, ROWS, EMB, EMB);
    gemm_dbuf<0><<<gemmE, 256, GEMM_SMEM>>>(xln, wv, bv, nullptr, v, ROWS, EMB, EMB);
    // 3) attention
    scores_wmma<<<dim3(4, 4, BH), 256, SCORES_SMEM>>>(q, k, scores);
    softmax_kernel<<<BH * SEQ, 128>>>(scores);
    av_wmma<<<dim3(4, BH), 256, AV_SMEM>>>(scores, v, attn);
    // 4) output projection + bias + residual
    gemm_dbuf<2><<<gemmE, 256, GEMM_SMEM>>>(attn, wo, bo, input, x, ROWS, EMB, EMB);
    // 5) LN2 (into xln, reused)
    ln_kernel<<<ROWS, 256>>>(x, ln2_g, ln2_b, xln);
    // 6) MLP up + bias + GELU
    gemm_dbuf<1><<<gemmF, 256, GEMM_SMEM>>>(xln, w1, b1, nullptr, h, ROWS, FF, EMB);
    // 7) MLP down + bias + residual -> out
    gemm_dbuf<2><<<gemmE, 256, GEMM_SMEM>>>(h, w2, b2, x, out, ROWS, EMB, FF);
}

// round 9
// speedup vs baseline: 1.2203x; 1.0193x over previous
#include <cuda_runtime.h>
#include <cuda_bf16.h>
#include <mma.h>
#include <math.h>
#include <cstdint>

using namespace nvcuda;

// Problem dims
#define BATCH 16
#define SEQ   512
#define EMB   1024
#define FF    4096
#define HEADS 16
#define HDIM  64
#define ROWS  (BATCH*SEQ)        // 8192
#define BH    (BATCH*HEADS)      // 256

// ---------------- scratch (device globals; no allocation allowed) ----------------
__device__ float g_xln[ROWS*EMB];
__device__ float g_q[ROWS*EMB];
__device__ float g_k[ROWS*EMB];
__device__ float g_v[ROWS*EMB];
__device__ float g_attn[ROWS*EMB];
__device__ float g_x[ROWS*EMB];
__device__ float g_h[ROWS*FF];
__device__ float g_scores[(size_t)BH*SEQ*SEQ];
// tf32-rounded weights: wq,wk,wv,wo (1M each), w1 (4M), w2 (4M) floats
__device__ float g_wR[12*1024*1024];

// ---------------- helpers ----------------
__device__ __forceinline__ void cp_async16(void* smem_dst, const void* gsrc) {
    unsigned s = (unsigned)__cvta_generic_to_shared(smem_dst);
    asm volatile("cp.async.cg.shared.global [%0], [%1], 16;\n" :: "r"(s), "l"(gsrc));
}
__device__ __forceinline__ void cp_commit() {
    asm volatile("cp.async.commit_group;\n");
}
__device__ __forceinline__ float gelu_exact(float y) {
    return 0.5f * y * (1.0f + erff(y * 0.70710678118654752f));
}
__device__ __forceinline__ float r32(float x) {        // RN round to tf32
    return wmma::__float_to_tf32(x);
}

// ---------------- weight rounding: out[i] = tf32(in[i]) ----------------
__global__ void round_tf32_kernel(const float* __restrict__ in, float* __restrict__ out) {
    size_t i = (size_t)blockIdx.x * blockDim.x + threadIdx.x;
    float4 v = reinterpret_cast<const float4*>(in)[i];
    v.x = r32(v.x); v.y = r32(v.y); v.z = r32(v.z); v.w = r32(v.w);
    reinterpret_cast<float4*>(out)[i] = v;
}

// ---------------- LayerNorm: output tf32-rounded (feeds GEMM A) ----------------
__global__ void ln_kernel(const float* __restrict__ in, const float* __restrict__ gam,
                          const float* __restrict__ bet, float* __restrict__ out) {
    int row = blockIdx.x;
    int t = threadIdx.x;
    const float4* inr = reinterpret_cast<const float4*>(in + (size_t)row * EMB);
    float4 x = inr[t];
    float s  = x.x + x.y + x.z + x.w;
    float sq = x.x*x.x + x.y*x.y + x.z*x.z + x.w*x.w;
    #pragma unroll
    for (int o = 16; o > 0; o >>= 1) {
        s  += __shfl_xor_sync(0xffffffffu, s,  o);
        sq += __shfl_xor_sync(0xffffffffu, sq, o);
    }
    __shared__ float sa[8], sb[8];
    int w = t >> 5, l = t & 31;
    if (l == 0) { sa[w] = s; sb[w] = sq; }
    __syncthreads();
    s = 0.f; sq = 0.f;
    #pragma unroll
    for (int i = 0; i < 8; i++) { s += sa[i]; sq += sb[i]; }
    float mean = s * (1.0f / EMB);
    float var  = sq * (1.0f / EMB) - mean * mean;
    float rstd = rsqrtf(var + 1e-5f);
    float4 g4 = reinterpret_cast<const float4*>(gam)[t];
    float4 b4 = reinterpret_cast<const float4*>(bet)[t];
    float4 o4;
    o4.x = r32((x.x - mean) * rstd * g4.x + b4.x);
    o4.y = r32((x.y - mean) * rstd * g4.y + b4.y);
    o4.z = r32((x.z - mean) * rstd * g4.z + b4.z);
    o4.w = r32((x.w - mean) * rstd * g4.w + b4.w);
    reinterpret_cast<float4*>(out + (size_t)row * EMB)[t] = o4;
}

// ---------------- TF32 GEMM, double-buffered cp.async, fused epilogue ----------------
// Inputs must be tf32-pre-rounded. No in-loop cvt.
// EPI: 0 = +bias, round out (QKV)   1 = +bias, GELU, round out (h)
// EPI: 2 = +bias, +res, full fp32 out (x, out)
#define ALD 36
#define BLD 132
#define GEMM_SMEM ((2*128*ALD + 2*32*BLD) * 4)   // 70656 bytes

template<int EPI>
__global__ __launch_bounds__(256, 2)
void gemm_dbuf(const float* __restrict__ A, const float* __restrict__ B,
               const float* __restrict__ bias, const float* __restrict__ res,
               float* __restrict__ C, int M, int N, int K) {
    extern __shared__ float smbuf[];
    float* As[2] = { smbuf, smbuf + 128*ALD };
    float* Bs[2] = { smbuf + 2*128*ALD, smbuf + 2*128*ALD + 32*BLD };
    float* Cs = smbuf;   // epilogue alias: [128][BLD]

    const int m0 = blockIdx.y * 128;
    const int n0 = blockIdx.x * 128;
    const int tid = threadIdx.x;
    const int warp = tid >> 5;
    const int wm = warp >> 2;      // 0..1
    const int wn = warp & 3;       // 0..3

    wmma::fragment<wmma::accumulator, 16, 16, 8, float> acc[4][2];
    #pragma unroll
    for (int i = 0; i < 4; i++)
        #pragma unroll
        for (int j = 0; j < 2; j++)
            wmma::fill_fragment(acc[i][j], 0.0f);

    auto load_stage = [&](int st, int k0) {
        #pragma unroll
        for (int p = 0; p < 4; p++) {              // A: 128 x 8 float4
            int idx = tid + p * 256;
            int r = idx >> 3, c = (idx & 7) << 2;
            cp_async16(As[st] + r * ALD + c, A + (size_t)(m0 + r) * K + k0 + c);
        }
        #pragma unroll
        for (int p = 0; p < 4; p++) {              // B: 32 x 32 float4
            int idx = tid + p * 256;
            int r = idx >> 5, c = (idx & 31) << 2;
            cp_async16(Bs[st] + r * BLD + c, B + (size_t)(k0 + r) * N + n0 + c);
        }
        cp_commit();
    };

    const int NT = K >> 5;
    load_stage(0, 0);

    for (int kt = 0; kt < NT; kt++) {
        if (kt + 1 < NT) {
            load_stage((kt + 1) & 1, (kt + 1) << 5);
            asm volatile("cp.async.wait_group 1;\n");
        } else {
            asm volatile("cp.async.wait_group 0;\n");
        }
        __syncthreads();
        const float* as = As[kt & 1];
        const float* bs = Bs[kt & 1];
        #pragma unroll
        for (int k8 = 0; k8 < 4; k8++) {
            wmma::fragment<wmma::matrix_a, 16, 16, 8, wmma::precision::tf32, wmma::row_major> af[4];
            wmma::fragment<wmma::matrix_b, 16, 16, 8, wmma::precision::tf32, wmma::row_major> bf[2];
            #pragma unroll
            for (int i = 0; i < 4; i++)
                wmma::load_matrix_sync(af[i], as + (wm * 64 + i * 16) * ALD + k8 * 8, ALD);
            #pragma unroll
            for (int j = 0; j < 2; j++)
                wmma::load_matrix_sync(bf[j], bs + (k8 * 8) * BLD + wn * 32 + j * 16, BLD);
            #pragma unroll
            for (int i = 0; i < 4; i++)
                #pragma unroll
                for (int j = 0; j < 2; j++)
                    wmma::mma_sync(acc[i][j], af[i], bf[j], acc[i][j]);
        }
        __syncthreads();
    }

    // epilogue: acc -> smem -> (bias / gelu / res) -> global
    #pragma unroll
    for (int i = 0; i < 4; i++)
        #pragma unroll
        for (int j = 0; j < 2; j++)
            wmma::store_matrix_sync(Cs + (wm * 64 + i * 16) * BLD + wn * 32 + j * 16,
                                    acc[i][j], BLD, wmma::mem_row_major);
    __syncthreads();

    #pragma unroll
    for (int p = 0; p < 16; p++) {
        int idx = tid + p * 256;              // 128 rows x 32 float4
        int r = idx >> 5, c = (idx & 31) << 2;
        float4 v = *reinterpret_cast<const float4*>(Cs + r * BLD + c);
        float4 b = *reinterpret_cast<const float4*>(bias + n0 + c);
        v.x += b.x; v.y += b.y; v.z += b.z; v.w += b.w;
        if (EPI == 1) {
            v.x = gelu_exact(v.x); v.y = gelu_exact(v.y);
            v.z = gelu_exact(v.z); v.w = gelu_exact(v.w);
        }
        if (EPI == 0 || EPI == 1) {            // output feeds another GEMM: pre-round
            v.x = r32(v.x); v.y = r32(v.y); v.z = r32(v.z); v.w = r32(v.w);
        }
        if (EPI == 2) {
            float4 rr = *reinterpret_cast<const float4*>(res + (size_t)(m0 + r) * N + n0 + c);
            v.x += rr.x; v.y += rr.y; v.z += rr.z; v.w += rr.w;
        }
        *reinterpret_cast<float4*>(C + (size_t)(m0 + r) * N + n0 + c) = v;
    }
}

// ---------------- attention scores = (Q K^T) * 1/8, TF32 wmma (Q,K pre-rounded) ----------------
#define QLD 68
#define SCORES_SMEM (2*128*QLD*4)   // 69632

__global__ __launch_bounds__(256, 2)
void scores_wmma(const float* __restrict__ q, const float* __restrict__ k,
                 float* __restrict__ s) {
    extern __shared__ float smbuf[];
    float* Qs = smbuf;            // [128][QLD]
    float* Ks = smbuf + 128*QLD;  // [128][QLD]
    int bh = blockIdx.z;
    int b = bh >> 4, h = bh & 15;
    int q0 = blockIdx.y * 128, k0 = blockIdx.x * 128;
    int tid = threadIdx.x;
    const float* qbase = q + (size_t)(b * SEQ + q0) * EMB + h * HDIM;
    const float* kbase = k + (size_t)(b * SEQ + k0) * EMB + h * HDIM;
    #pragma unroll
    for (int p = 0; p < 8; p++) {
        int idx = tid + p * 256;               // 128 rows x 16 float4
        int r = idx >> 4, c = (idx & 15) << 2;
        *reinterpret_cast<float4*>(Qs + r * QLD + c) =
            *reinterpret_cast<const float4*>(qbase + (size_t)r * EMB + c);
        *reinterpret_cast<float4*>(Ks + r * QLD + c) =
            *reinterpret_cast<const float4*>(kbase + (size_t)r * EMB + c);
    }
    __syncthreads();

    int warp = tid >> 5, wm = warp >> 2, wn = warp & 3;
    wmma::fragment<wmma::accumulator, 16, 16, 8, float> acc[4][2];
    #pragma unroll
    for (int i = 0; i < 4; i++)
        #pragma unroll
        for (int j = 0; j < 2; j++)
            wmma::fill_fragment(acc[i][j], 0.0f);

    #pragma unroll
    for (int k8 = 0; k8 < 8; k8++) {
        wmma::fragment<wmma::matrix_a, 16, 16, 8, wmma::precision::tf32, wmma::row_major> af[4];
        wmma::fragment<wmma::matrix_b, 16, 16, 8, wmma::precision::tf32, wmma::col_major> bf[2];
        #pragma unroll
        for (int i = 0; i < 4; i++)
            wmma::load_matrix_sync(af[i], Qs + (wm * 64 + i * 16) * QLD + k8 * 8, QLD);
        #pragma unroll
        for (int j = 0; j < 2; j++)
            wmma::load_matrix_sync(bf[j], Ks + (wn * 32 + j * 16) * QLD + k8 * 8, QLD);
        #pragma unroll
        for (int i = 0; i < 4; i++)
            #pragma unroll
            for (int j = 0; j < 2; j++)
                wmma::mma_sync(acc[i][j], af[i], bf[j], acc[i][j]);
    }

    #pragma unroll
    for (int i = 0; i < 4; i++)
        #pragma unroll
        for (int j = 0; j < 2; j++) {
            #pragma unroll
            for (int e = 0; e < acc[i][j].num_elements; e++)
                acc[i][j].x[e] *= 0.125f;
            wmma::store_matrix_sync(
                s + ((size_t)bh * SEQ + q0 + wm * 64 + i * 16) * SEQ + k0 + wn * 32 + j * 16,
                acc[i][j], SEQ, wmma::mem_row_major);
        }
}

// ---------------- softmax over rows of 512; output tf32-rounded (feeds AV) ----------------
__global__ void softmax_kernel(float* __restrict__ s) {
    size_t row = blockIdx.x;
    float* p = s + row * SEQ;
    int t = threadIdx.x;
    float4 x = reinterpret_cast<float4*>(p)[t];
    float m = fmaxf(fmaxf(x.x, x.y), fmaxf(x.z, x.w));
    #pragma unroll
    for (int o = 16; o > 0; o >>= 1) m = fmaxf(m, __shfl_xor_sync(0xffffffffu, m, o));
    __shared__ float sm[4], ss[4];
    int w = t >> 5, l = t & 31;
    if (l == 0) sm[w] = m;
    __syncthreads();
    m = fmaxf(fmaxf(sm[0], sm[1]), fmaxf(sm[2], sm[3]));
    x.x = __expf(x.x - m); x.y = __expf(x.y - m);
    x.z = __expf(x.z - m); x.w = __expf(x.w - m);
    float sum = x.x + x.y + x.z + x.w;
    #pragma unroll
    for (int o = 16; o > 0; o >>= 1) sum += __shfl_xor_sync(0xffffffffu, sum, o);
    if (l == 0) ss[w] = sum;
    __syncthreads();
    sum = ss[0] + ss[1] + ss[2] + ss[3];
    float inv = 1.0f / sum;
    x.x = r32(x.x * inv); x.y = r32(x.y * inv);
    x.z = r32(x.z * inv); x.w = r32(x.w * inv);
    reinterpret_cast<float4*>(p)[t] = x;
}

// ---------------- AV: out = P V, TF32 wmma (P,V pre-rounded; output rounded) ----------------
#define AV_SMEM ((128*QLD + 64*QLD) * 4)   // 52224

__global__ __launch_bounds__(256, 2)
void av_wmma(const float* __restrict__ s, const float* __restrict__ v,
             float* __restrict__ o) {
    extern __shared__ float smbuf[];
    float* Ps = smbuf;            // [128][QLD]
    float* Vs = smbuf + 128*QLD;  // [64][QLD]
    int bh = blockIdx.y;
    int b = bh >> 4, h = bh & 15;
    int q0 = blockIdx.x * 128;
    int tid = threadIdx.x;
    int warp = tid >> 5, wm = warp >> 1, wn = warp & 1;

    wmma::fragment<wmma::accumulator, 16, 16, 8, float> acc[2][2];
    #pragma unroll
    for (int i = 0; i < 2; i++)
        #pragma unroll
        for (int j = 0; j < 2; j++)
            wmma::fill_fragment(acc[i][j], 0.0f);

    for (int kc = 0; kc < SEQ; kc += 64) {
        #pragma unroll
        for (int p = 0; p < 8; p++) {              // P: 128 x 16 float4
            int idx = tid + p * 256;
            int r = idx >> 4, c = (idx & 15) << 2;
            *reinterpret_cast<float4*>(Ps + r * QLD + c) =
                *reinterpret_cast<const float4*>(s + ((size_t)bh * SEQ + q0 + r) * SEQ + kc + c);
        }
        #pragma unroll
        for (int p = 0; p < 4; p++) {              // V: 64 x 16 float4
            int idx = tid + p * 256;
            int r = idx >> 4, c = (idx & 15) << 2;
            *reinterpret_cast<float4*>(Vs + r * QLD + c) =
                *reinterpret_cast<const float4*>(v + (size_t)(b * SEQ + kc + r) * EMB + h * HDIM + c);
        }
        __syncthreads();
        #pragma unroll
        for (int k8 = 0; k8 < 8; k8++) {
            wmma::fragment<wmma::matrix_a, 16, 16, 8, wmma::precision::tf32, wmma::row_major> af[2];
            wmma::fragment<wmma::matrix_b, 16, 16, 8, wmma::precision::tf32, wmma::row_major> bf[2];
            #pragma unroll
            for (int i = 0; i < 2; i++)
                wmma::load_matrix_sync(af[i], Ps + (wm * 32 + i * 16) * QLD + k8 * 8, QLD);
            #pragma unroll
            for (int j = 0; j < 2; j++)
                wmma::load_matrix_sync(bf[j], Vs + (k8 * 8) * QLD + wn * 32 + j * 16, QLD);
            #pragma unroll
            for (int i = 0; i < 2; i++)
                #pragma unroll
                for (int j = 0; j < 2; j++)
                    wmma::mma_sync(acc[i][j], af[i], bf[j], acc[i][j]);
        }
        __syncthreads();
    }

    #pragma unroll
    for (int i = 0; i < 2; i++)
        #pragma unroll
        for (int j = 0; j < 2; j++) {
            #pragma unroll
            for (int e = 0; e < acc[i][j].num_elements; e++)
                acc[i][j].x[e] = r32(acc[i][j].x[e]);   // feeds o-proj GEMM A
            wmma::store_matrix_sync(
                o + (size_t)(b * SEQ + q0 + wm * 32 + i * 16) * EMB + h * HDIM + wn * 32 + j * 16,
                acc[i][j], EMB, wmma::mem_row_major);
        }
}

// ---------------- driver ----------------
extern "C" void kernel_launch(void* const* d_in, const int* in_sizes, int n_in,
                              void* d_out, int out_size) {
    const float* input = (const float*)d_in[0];
    const float* ln1_g = (const float*)d_in[1];
    const float* ln1_b = (const float*)d_in[2];
    const float* wq    = (const float*)d_in[3];
    const float* bq    = (const float*)d_in[4];
    const float* wk    = (const float*)d_in[5];
    const float* bk    = (const float*)d_in[6];
    const float* wv    = (const float*)d_in[7];
    const float* bv    = (const float*)d_in[8];
    const float* wo    = (const float*)d_in[9];
    const float* bo    = (const float*)d_in[10];
    const float* ln2_g = (const float*)d_in[11];
    const float* ln2_b = (const float*)d_in[12];
    const float* w1    = (const float*)d_in[13];
    const float* b1    = (const float*)d_in[14];
    const float* w2    = (const float*)d_in[15];
    const float* b2    = (const float*)d_in[16];
    float* out = (float*)d_out;

    float *xln, *q, *k, *v, *attn, *x, *h, *scores, *wR;
    cudaGetSymbolAddress((void**)&xln,    g_xln);
    cudaGetSymbolAddress((void**)&q,      g_q);
    cudaGetSymbolAddress((void**)&k,      g_k);
    cudaGetSymbolAddress((void**)&v,      g_v);
    cudaGetSymbolAddress((void**)&attn,   g_attn);
    cudaGetSymbolAddress((void**)&x,      g_x);
    cudaGetSymbolAddress((void**)&h,      g_h);
    cudaGetSymbolAddress((void**)&scores, g_scores);
    cudaGetSymbolAddress((void**)&wR,     g_wR);

    float* wqR = wR;                       // [1024,1024]
    float* wkR = wR + 1*1024*1024;
    float* wvR = wR + 2*1024*1024;
    float* woR = wR + 3*1024*1024;
    float* w1R = wR + 4*1024*1024;         // [1024,4096]
    float* w2R = wR + 8*1024*1024;         // [4096,1024]

    cudaFuncSetAttribute(gemm_dbuf<0>, cudaFuncAttributeMaxDynamicSharedMemorySize, GEMM_SMEM);
    cudaFuncSetAttribute(gemm_dbuf<1>, cudaFuncAttributeMaxDynamicSharedMemorySize, GEMM_SMEM);
    cudaFuncSetAttribute(gemm_dbuf<2>, cudaFuncAttributeMaxDynamicSharedMemorySize, GEMM_SMEM);
    cudaFuncSetAttribute(scores_wmma,  cudaFuncAttributeMaxDynamicSharedMemorySize, SCORES_SMEM);
    cudaFuncSetAttribute(av_wmma,      cudaFuncAttributeMaxDynamicSharedMemorySize, AV_SMEM);

    // 0) tf32-round all weights (one pass each)
    round_tf32_kernel<<<1024, 256>>>(wq, wqR);
    round_tf32_kernel<<<1024, 256>>>(wk, wkR);
    round_tf32_kernel<<<1024, 256>>>(wv, wvR);
    round_tf32_kernel<<<1024, 256>>>(wo, woR);
    round_tf32_kernel<<<4096, 256>>>(w1, w1R);
    round_tf32_kernel<<<4096, 256>>>(w2, w2R);

    dim3 gemmE(EMB / 128, ROWS / 128);    // (8, 64)
    dim3 gemmF(FF / 128, ROWS / 128);     // (32, 64)

    // 1) LN1 (output tf32-rounded)
    ln_kernel<<<ROWS, 256>>>(input, ln1_g, ln1_b, xln);
    // 2) QKV projections, fused bias, rounded outputs
    gemm_dbuf<0><<<gemmE, 256, GEMM_SMEM>>>(xln, wqR, bq, nullptr, q, ROWS, EMB, EMB);
    gemm_dbuf<0><<<gemmE, 256, GEMM_SMEM>>>(xln, wkR, bk, nullptr, k, ROWS, EMB, EMB);
    gemm_dbuf<0><<<gemmE, 256, GEMM_SMEM>>>(xln, wvR, bv, nullptr, v, ROWS, EMB, EMB);
    // 3) attention
    scores_wmma<<<dim3(4, 4, BH), 256, SCORES_SMEM>>>(q, k, scores);
    softmax_kernel<<<BH * SEQ, 128>>>(scores);
    av_wmma<<<dim3(4, BH), 256, AV_SMEM>>>(scores, v, attn);
    // 4) output projection + bias + residual (full fp32 out)
    gemm_dbuf<2><<<gemmE, 256, GEMM_SMEM>>>(attn, woR, bo, input, x, ROWS, EMB, EMB);
    // 5) LN2 (rounded)
    ln_kernel<<<ROWS, 256>>>(x, ln2_g, ln2_b, xln);
    // 6) MLP up + bias + GELU (rounded)
    gemm_dbuf<1><<<gemmF, 256, GEMM_SMEM>>>(xln, w1R, b1, nullptr, h, ROWS, FF, EMB);
    // 7) MLP down + bias + residual -> out (full fp32)
    gemm_dbuf<2><<<gemmE, 256, GEMM_SMEM>>>(h, w2R, b2, x, out, ROWS, EMB, FF);
}

// round 10
// speedup vs baseline: 3.4280x; 2.8092x over previous
#include <cuda_runtime.h>
#include <cuda_fp16.h>
#include <mma.h>
#include <math.h>
#include <cstdint>

using namespace nvcuda;

// Problem dims
#define BATCH 16
#define SEQ   512
#define EMB   1024
#define FF    4096
#define HEADS 16
#define HDIM  64
#define ROWS  (BATCH*SEQ)        // 8192
#define BH    (BATCH*HEADS)      // 256

// ---------------- scratch (device globals; no allocation allowed) ----------------
__device__ __half g_wH[12*1024*1024];          // wq,wk,wv,wo (1M ea), w1 (4M), w2 (4M)
__device__ __half g_xh[ROWS*EMB];              // LN out (half)
__device__ __half g_qh[ROWS*EMB];
__device__ __half g_kh[ROWS*EMB];
__device__ __half g_vh[ROWS*EMB];
__device__ __half g_ah[ROWS*EMB];              // attention out (half)
__device__ __half g_hh[ROWS*FF];               // MLP hidden (half)
__device__ __half g_ph[(size_t)BH*SEQ*SEQ];    // softmax probs (half)
__device__ float  g_scores[(size_t)BH*SEQ*SEQ];
__device__ float  g_x[ROWS*EMB];               // residual stream (fp32)

// ---------------- helpers ----------------
__device__ __forceinline__ void cp_async16(void* smem_dst, const void* gsrc) {
    unsigned s = (unsigned)__cvta_generic_to_shared(smem_dst);
    asm volatile("cp.async.cg.shared.global [%0], [%1], 16;\n" :: "r"(s), "l"(gsrc));
}
__device__ __forceinline__ void cp_commit() {
    asm volatile("cp.async.commit_group;\n");
}
__device__ __forceinline__ float gelu_exact(float y) {
    return 0.5f * y * (1.0f + erff(y * 0.70710678118654752f));
}
__device__ __forceinline__ void st_half4(__half* p, float4 v) {
    __half2* p2 = reinterpret_cast<__half2*>(p);
    p2[0] = __floats2half2_rn(v.x, v.y);
    p2[1] = __floats2half2_rn(v.z, v.w);
}

// ---------------- weight conversion: half(in[i]) ----------------
__global__ void cvt_half_kernel(const float* __restrict__ in, __half* __restrict__ out) {
    size_t i = (size_t)blockIdx.x * blockDim.x + threadIdx.x;
    float4 v = reinterpret_cast<const float4*>(in)[i];
    st_half4(out + i * 4, v);
}

// ---------------- LayerNorm: fp32 in, half out ----------------
__global__ void ln_kernel(const float* __restrict__ in, const float* __restrict__ gam,
                          const float* __restrict__ bet, __half* __restrict__ out) {
    int row = blockIdx.x;
    int t = threadIdx.x;
    const float4* inr = reinterpret_cast<const float4*>(in + (size_t)row * EMB);
    float4 x = inr[t];
    float s  = x.x + x.y + x.z + x.w;
    float sq = x.x*x.x + x.y*x.y + x.z*x.z + x.w*x.w;
    #pragma unroll
    for (int o = 16; o > 0; o >>= 1) {
        s  += __shfl_xor_sync(0xffffffffu, s,  o);
        sq += __shfl_xor_sync(0xffffffffu, sq, o);
    }
    __shared__ float sa[8], sb[8];
    int w = t >> 5, l = t & 31;
    if (l == 0) { sa[w] = s; sb[w] = sq; }
    __syncthreads();
    s = 0.f; sq = 0.f;
    #pragma unroll
    for (int i = 0; i < 8; i++) { s += sa[i]; sq += sb[i]; }
    float mean = s * (1.0f / EMB);
    float var  = sq * (1.0f / EMB) - mean * mean;
    float rstd = rsqrtf(var + 1e-5f);
    float4 g4 = reinterpret_cast<const float4*>(gam)[t];
    float4 b4 = reinterpret_cast<const float4*>(bet)[t];
    float4 o4;
    o4.x = (x.x - mean) * rstd * g4.x + b4.x;
    o4.y = (x.y - mean) * rstd * g4.y + b4.y;
    o4.z = (x.z - mean) * rstd * g4.z + b4.z;
    o4.w = (x.w - mean) * rstd * g4.w + b4.w;
    st_half4(out + (size_t)row * EMB + t * 4, o4);
}

// ---------------- FP16 GEMM, double-buffered cp.async, BK=64, fused epilogue ----------
// C[M,N] = A[M,K]*B[K,N]; A,B half, accum fp32. Block 128x128, 8 warps (2x4),
// warp tile 64x32 = 4x2 m16n16k16 frags.
// EPI: 0 = +bias -> half    1 = +bias,GELU -> half    2 = +bias,+res -> float
#define ALD 72     // halves per A row (64+8)
#define BLD 136    // halves per B row (128+8)
#define STAGE_B (128*ALD*2 + 64*BLD*2)            // 35840 bytes
#define GEMM_SMEM 71680                           // max(2*STAGE_B, 128*132*4)

template<int EPI>
__global__ __launch_bounds__(256, 2)
void gemm_h(const __half* __restrict__ A, const __half* __restrict__ B,
            const float* __restrict__ bias, const float* __restrict__ res,
            void* __restrict__ Cout, int M, int N, int K) {
    extern __shared__ char smraw[];
    __half* As[2] = { (__half*)smraw, (__half*)(smraw + STAGE_B) };
    __half* Bs[2] = { (__half*)(smraw + 128*ALD*2), (__half*)(smraw + STAGE_B + 128*ALD*2) };
    float* Cs = (float*)smraw;   // epilogue alias [128][132]

    const int m0 = blockIdx.y * 128;
    const int n0 = blockIdx.x * 128;
    const int tid = threadIdx.x;
    const int warp = tid >> 5;
    const int wm = warp >> 2;      // 0..1
    const int wn = warp & 3;       // 0..3

    wmma::fragment<wmma::accumulator, 16, 16, 16, float> acc[4][2];
    #pragma unroll
    for (int i = 0; i < 4; i++)
        #pragma unroll
        for (int j = 0; j < 2; j++)
            wmma::fill_fragment(acc[i][j], 0.0f);

    auto load_stage = [&](int st, int k0) {
        #pragma unroll
        for (int p = 0; p < 4; p++) {              // A: 128 rows x 8 chunks (8 halves)
            int idx = tid + p * 256;
            int r = idx >> 3, c = (idx & 7) << 3;
            cp_async16(As[st] + r * ALD + c, A + (size_t)(m0 + r) * K + k0 + c);
        }
        #pragma unroll
        for (int p = 0; p < 4; p++) {              // B: 64 rows x 16 chunks
            int idx = tid + p * 256;
            int r = idx >> 4, c = (idx & 15) << 3;
            cp_async16(Bs[st] + r * BLD + c, B + (size_t)(k0 + r) * N + n0 + c);
        }
        cp_commit();
    };

    const int NT = K >> 6;
    load_stage(0, 0);

    for (int kt = 0; kt < NT; kt++) {
        if (kt + 1 < NT) {
            load_stage((kt + 1) & 1, (kt + 1) << 6);
            asm volatile("cp.async.wait_group 1;\n");
        } else {
            asm volatile("cp.async.wait_group 0;\n");
        }
        __syncthreads();
        const __half* as = As[kt & 1];
        const __half* bs = Bs[kt & 1];
        #pragma unroll
        for (int ks = 0; ks < 4; ks++) {
            wmma::fragment<wmma::matrix_a, 16, 16, 16, __half, wmma::row_major> af[4];
            wmma::fragment<wmma::matrix_b, 16, 16, 16, __half, wmma::row_major> bf[2];
            #pragma unroll
            for (int i = 0; i < 4; i++)
                wmma::load_matrix_sync(af[i], as + (wm * 64 + i * 16) * ALD + ks * 16, ALD);
            #pragma unroll
            for (int j = 0; j < 2; j++)
                wmma::load_matrix_sync(bf[j], bs + (ks * 16) * BLD + wn * 32 + j * 16, BLD);
            #pragma unroll
            for (int i = 0; i < 4; i++)
                #pragma unroll
                for (int j = 0; j < 2; j++)
                    wmma::mma_sync(acc[i][j], af[i], bf[j], acc[i][j]);
        }
        __syncthreads();
    }

    // epilogue via smem
    #pragma unroll
    for (int i = 0; i < 4; i++)
        #pragma unroll
        for (int j = 0; j < 2; j++)
            wmma::store_matrix_sync(Cs + (wm * 64 + i * 16) * 132 + wn * 32 + j * 16,
                                    acc[i][j], 132, wmma::mem_row_major);
    __syncthreads();

    #pragma unroll
    for (int p = 0; p < 16; p++) {
        int idx = tid + p * 256;              // 128 rows x 32 float4
        int r = idx >> 5, c = (idx & 31) << 2;
        float4 v = *reinterpret_cast<const float4*>(Cs + r * 132 + c);
        float4 b = *reinterpret_cast<const float4*>(bias + n0 + c);
        v.x += b.x; v.y += b.y; v.z += b.z; v.w += b.w;
        if (EPI == 1) {
            v.x = gelu_exact(v.x); v.y = gelu_exact(v.y);
            v.z = gelu_exact(v.z); v.w = gelu_exact(v.w);
        }
        if (EPI == 2) {
            float4 rr = *reinterpret_cast<const float4*>(res + (size_t)(m0 + r) * N + n0 + c);
            v.x += rr.x; v.y += rr.y; v.z += rr.z; v.w += rr.w;
            *reinterpret_cast<float4*>((float*)Cout + (size_t)(m0 + r) * N + n0 + c) = v;
        } else {
            st_half4((__half*)Cout + (size_t)(m0 + r) * N + n0 + c, v);
        }
    }
}

// ---------------- attention scores = (Q K^T) * 1/8, fp16 wmma ----------------
#define QLD 72
#define SCORES_SMEM (2*128*QLD*2)   // 36864

__global__ __launch_bounds__(256, 2)
void scores_h(const __half* __restrict__ q, const __half* __restrict__ k,
              float* __restrict__ s) {
    extern __shared__ char smraw[];
    __half* Qs = (__half*)smraw;              // [128][QLD]
    __half* Ks = (__half*)smraw + 128*QLD;    // [128][QLD]
    int bh = blockIdx.z;
    int b = bh >> 4, h = bh & 15;
    int q0 = blockIdx.y * 128, k0 = blockIdx.x * 128;
    int tid = threadIdx.x;
    const __half* qbase = q + (size_t)(b * SEQ + q0) * EMB + h * HDIM;
    const __half* kbase = k + (size_t)(b * SEQ + k0) * EMB + h * HDIM;
    #pragma unroll
    for (int p = 0; p < 4; p++) {
        int idx = tid + p * 256;              // 128 rows x 8 chunks (8 halves)
        int r = idx >> 3, c = (idx & 7) << 3;
        *reinterpret_cast<float4*>(Qs + r * QLD + c) =
            *reinterpret_cast<const float4*>(qbase + (size_t)r * EMB + c);
        *reinterpret_cast<float4*>(Ks + r * QLD + c) =
            *reinterpret_cast<const float4*>(kbase + (size_t)r * EMB + c);
    }
    __syncthreads();

    int warp = tid >> 5, wm = warp >> 2, wn = warp & 3;
    wmma::fragment<wmma::accumulator, 16, 16, 16, float> acc[4][2];
    #pragma unroll
    for (int i = 0; i < 4; i++)
        #pragma unroll
        for (int j = 0; j < 2; j++)
            wmma::fill_fragment(acc[i][j], 0.0f);

    #pragma unroll
    for (int ks = 0; ks < 4; ks++) {
        wmma::fragment<wmma::matrix_a, 16, 16, 16, __half, wmma::row_major> af[4];
        wmma::fragment<wmma::matrix_b, 16, 16, 16, __half, wmma::col_major> bf[2];
        #pragma unroll
        for (int i = 0; i < 4; i++)
            wmma::load_matrix_sync(af[i], Qs + (wm * 64 + i * 16) * QLD + ks * 16, QLD);
        #pragma unroll
        for (int j = 0; j < 2; j++)
            wmma::load_matrix_sync(bf[j], Ks + (wn * 32 + j * 16) * QLD + ks * 16, QLD);
        #pragma unroll
        for (int i = 0; i < 4; i++)
            #pragma unroll
            for (int j = 0; j < 2; j++)
                wmma::mma_sync(acc[i][j], af[i], bf[j], acc[i][j]);
    }

    #pragma unroll
    for (int i = 0; i < 4; i++)
        #pragma unroll
        for (int j = 0; j < 2; j++) {
            #pragma unroll
            for (int e = 0; e < acc[i][j].num_elements; e++)
                acc[i][j].x[e] *= 0.125f;
            wmma::store_matrix_sync(
                s + ((size_t)bh * SEQ + q0 + wm * 64 + i * 16) * SEQ + k0 + wn * 32 + j * 16,
                acc[i][j], SEQ, wmma::mem_row_major);
        }
}

// ---------------- softmax: fp32 scores in, half probs out ----------------
__global__ void softmax_kernel(const float* __restrict__ s, __half* __restrict__ ph) {
    size_t row = blockIdx.x;
    const float* p = s + row * SEQ;
    int t = threadIdx.x;
    float4 x = reinterpret_cast<const float4*>(p)[t];
    float m = fmaxf(fmaxf(x.x, x.y), fmaxf(x.z, x.w));
    #pragma unroll
    for (int o = 16; o > 0; o >>= 1) m = fmaxf(m, __shfl_xor_sync(0xffffffffu, m, o));
    __shared__ float sm[4], ss[4];
    int w = t >> 5, l = t & 31;
    if (l == 0) sm[w] = m;
    __syncthreads();
    m = fmaxf(fmaxf(sm[0], sm[1]), fmaxf(sm[2], sm[3]));
    x.x = __expf(x.x - m); x.y = __expf(x.y - m);
    x.z = __expf(x.z - m); x.w = __expf(x.w - m);
    float sum = x.x + x.y + x.z + x.w;
    #pragma unroll
    for (int o = 16; o > 0; o >>= 1) sum += __shfl_xor_sync(0xffffffffu, sum, o);
    if (l == 0) ss[w] = sum;
    __syncthreads();
    sum = ss[0] + ss[1] + ss[2] + ss[3];
    float inv = 1.0f / sum;
    x.x *= inv; x.y *= inv; x.z *= inv; x.w *= inv;
    st_half4(ph + row * SEQ + t * 4, x);
}

// ---------------- AV: attn = P V, fp16 wmma, half out ----------------
// grid (qtile=4, bh), 8 warps as 4x2, warp tile 32x32.
#define AV_SMEM 34816   // max(Ps+Vs = 128*72*2 + 64*72*2 = 27648, Cs 128*68*4 = 34816)

__global__ __launch_bounds__(256, 2)
void av_h(const __half* __restrict__ ph, const __half* __restrict__ v,
          __half* __restrict__ o) {
    extern __shared__ char smraw[];
    __half* Ps = (__half*)smraw;              // [128][QLD]
    __half* Vs = (__half*)smraw + 128*QLD;    // [64][QLD]
    float* Cs = (float*)smraw;                // epilogue alias [128][68]
    int bh = blockIdx.y;
    int b = bh >> 4, h = bh & 15;
    int q0 = blockIdx.x * 128;
    int tid = threadIdx.x;
    int warp = tid >> 5, wm = warp >> 1, wn = warp & 1;

    wmma::fragment<wmma::accumulator, 16, 16, 16, float> acc[2][2];
    #pragma unroll
    for (int i = 0; i < 2; i++)
        #pragma unroll
        for (int j = 0; j < 2; j++)
            wmma::fill_fragment(acc[i][j], 0.0f);

    for (int kc = 0; kc < SEQ; kc += 64) {
        #pragma unroll
        for (int p = 0; p < 4; p++) {          // P: 128 rows x 8 chunks
            int idx = tid + p * 256;
            int r = idx >> 3, c = (idx & 7) << 3;
            *reinterpret_cast<float4*>(Ps + r * QLD + c) =
                *reinterpret_cast<const float4*>(ph + ((size_t)bh * SEQ + q0 + r) * SEQ + kc + c);
        }
        #pragma unroll
        for (int p = 0; p < 2; p++) {          // V: 64 rows x 8 chunks
            int idx = tid + p * 256;
            int r = idx >> 3, c = (idx & 7) << 3;
            *reinterpret_cast<float4*>(Vs + r * QLD + c) =
                *reinterpret_cast<const float4*>(v + (size_t)(b * SEQ + kc + r) * EMB + h * HDIM + c);
        }
        __syncthreads();
        #pragma unroll
        for (int ks = 0; ks < 4; ks++) {
            wmma::fragment<wmma::matrix_a, 16, 16, 16, __half, wmma::row_major> af[2];
            wmma::fragment<wmma::matrix_b, 16, 16, 16, __half, wmma::row_major> bf[2];
            #pragma unroll
            for (int i = 0; i < 2; i++)
                wmma::load_matrix_sync(af[i], Ps + (wm * 32 + i * 16) * QLD + ks * 16, QLD);
            #pragma unroll
            for (int j = 0; j < 2; j++)
                wmma::load_matrix_sync(bf[j], Vs + (ks * 16) * QLD + wn * 32 + j * 16, QLD);
            #pragma unroll
            for (int i = 0; i < 2; i++)
                #pragma unroll
                for (int j = 0; j < 2; j++)
                    wmma::mma_sync(acc[i][j], af[i], bf[j], acc[i][j]);
        }
        __syncthreads();
    }

    // acc -> smem fp32 -> half global
    #pragma unroll
    for (int i = 0; i < 2; i++)
        #pragma unroll
        for (int j = 0; j < 2; j++)
            wmma::store_matrix_sync(Cs + (wm * 32 + i * 16) * 68 + wn * 32 + j * 16,
                                    acc[i][j], 68, wmma::mem_row_major);
    __syncthreads();
    #pragma unroll
    for (int p = 0; p < 8; p++) {
        int idx = tid + p * 256;              // 128 rows x 16 float4
        int r = idx >> 4, c = (idx & 15) << 2;
        float4 vv = *reinterpret_cast<const float4*>(Cs + r * 68 + c);
        st_half4(o + (size_t)(b * SEQ + q0 + r) * EMB + h * HDIM + c, vv);
    }
}

// ---------------- driver ----------------
extern "C" void kernel_launch(void* const* d_in, const int* in_sizes, int n_in,
                              void* d_out, int out_size) {
    const float* input = (const float*)d_in[0];
    const float* ln1_g = (const float*)d_in[1];
    const float* ln1_b = (const float*)d_in[2];
    const float* wq    = (const float*)d_in[3];
    const float* bq    = (const float*)d_in[4];
    const float* wk    = (const float*)d_in[5];
    const float* bk    = (const float*)d_in[6];
    const float* wv    = (const float*)d_in[7];
    const float* bv    = (const float*)d_in[8];
    const float* wo    = (const float*)d_in[9];
    const float* bo    = (const float*)d_in[10];
    const float* ln2_g = (const float*)d_in[11];
    const float* ln2_b = (const float*)d_in[12];
    const float* w1    = (const float*)d_in[13];
    const float* b1    = (const float*)d_in[14];
    const float* w2    = (const float*)d_in[15];
    const float* b2    = (const float*)d_in[16];
    float* out = (float*)d_out;

    __half *wH, *xh, *qh, *kh, *vh, *ah, *hh, *phh;
    float *scores, *x;
    cudaGetSymbolAddress((void**)&wH,     g_wH);
    cudaGetSymbolAddress((void**)&xh,     g_xh);
    cudaGetSymbolAddress((void**)&qh,     g_qh);
    cudaGetSymbolAddress((void**)&kh,     g_kh);
    cudaGetSymbolAddress((void**)&vh,     g_vh);
    cudaGetSymbolAddress((void**)&ah,     g_ah);
    cudaGetSymbolAddress((void**)&hh,     g_hh);
    cudaGetSymbolAddress((void**)&phh,    g_ph);
    cudaGetSymbolAddress((void**)&scores, g_scores);
    cudaGetSymbolAddress((void**)&x,      g_x);

    __half* wqH = wH;                       // [1024,1024]
    __half* wkH = wH + 1*1024*1024;
    __half* wvH = wH + 2*1024*1024;
    __half* woH = wH + 3*1024*1024;
    __half* w1H = wH + 4*1024*1024;         // [1024,4096]
    __half* w2H = wH + 8*1024*1024;         // [4096,1024]

    cudaFuncSetAttribute(gemm_h<0>, cudaFuncAttributeMaxDynamicSharedMemorySize, GEMM_SMEM);
    cudaFuncSetAttribute(gemm_h<1>, cudaFuncAttributeMaxDynamicSharedMemorySize, GEMM_SMEM);
    cudaFuncSetAttribute(gemm_h<2>, cudaFuncAttributeMaxDynamicSharedMemorySize, GEMM_SMEM);
    cudaFuncSetAttribute(scores_h,  cudaFuncAttributeMaxDynamicSharedMemorySize, SCORES_SMEM);
    cudaFuncSetAttribute(av_h,      cudaFuncAttributeMaxDynamicSharedMemorySize, AV_SMEM);

    // 0) weights -> half (one pass each)
    cvt_half_kernel<<<1024, 256>>>(wq, wqH);
    cvt_half_kernel<<<1024, 256>>>(wk, wkH);
    cvt_half_kernel<<<1024, 256>>>(wv, wvH);
    cvt_half_kernel<<<1024, 256>>>(wo, woH);
    cvt_half_kernel<<<4096, 256>>>(w1, w1H);
    cvt_half_kernel<<<4096, 256>>>(w2, w2H);

    dim3 gemmE(EMB / 128, ROWS / 128);    // (8, 64)
    dim3 gemmF(FF / 128, ROWS / 128);     // (32, 64)

    // 1) LN1 -> half
    ln_kernel<<<ROWS, 256>>>(input, ln1_g, ln1_b, xh);
    // 2) QKV projections, fused bias, half outputs
    gemm_h<0><<<gemmE, 256, GEMM_SMEM>>>(xh, wqH, bq, nullptr, qh, ROWS, EMB, EMB);
    gemm_h<0><<<gemmE, 256, GEMM_SMEM>>>(xh, wkH, bk, nullptr, kh, ROWS, EMB, EMB);
    gemm_h<0><<<gemmE, 256, GEMM_SMEM>>>(xh, wvH, bv, nullptr, vh, ROWS, EMB, EMB);
    // 3) attention
    scores_h<<<dim3(4, 4, BH), 256, SCORES_SMEM>>>(qh, kh, scores);
    softmax_kernel<<<BH * SEQ, 128>>>(scores, phh);
    av_h<<<dim3(4, BH), 256, AV_SMEM>>>(phh, vh, ah);
    // 4) output projection + bias + residual (fp32 out)
    gemm_h<2><<<gemmE, 256, GEMM_SMEM>>>(ah, woH, bo, input, x, ROWS, EMB, EMB);
    // 5) LN2 -> half
    ln_kernel<<<ROWS, 256>>>(x, ln2_g, ln2_b, xh);
    // 6) MLP up + bias + GELU -> half
    gemm_h<1><<<gemmF, 256, GEMM_SMEM>>>(xh, w1H, b1, nullptr, hh, ROWS, FF, EMB);
    // 7) MLP down + bias + residual -> out (fp32)
    gemm_h<2><<<gemmE, 256, GEMM_SMEM>>>(hh, w2H, b2, x, out, ROWS, EMB, FF);
}